// round 17
// baseline (speedup 1.0000x reference)
#include <cuda_runtime.h>
#include <cuda_bf16.h>
#include <cstdint>

#define NG      40
#define CPG     8
#define CCH     12
#define BB      4
#define HH_     64
#define WW_     128
#define DD_     48
#define HW      (HH_*WW_)         /* 8192 */
#define DHW     ((size_t)DD_*HW)  /* 393216 */

// Scratch (device globals — no allocation APIs)
// volume & x1 stored pre-split: packed uint32 = (bf16(ci_odd)<<16)|bf16(ci_even)
__device__ uint32_t g_volH[(size_t)BB*32*DD_*HH_*WW_];
__device__ uint32_t g_volL[(size_t)BB*32*DD_*HH_*WW_];
__device__ uint32_t g_x1H [(size_t)BB*16*DD_*HH_*WW_];
__device__ uint32_t g_x1L [(size_t)BB*16*DD_*HH_*WW_];
// B fragments: [tap 27][ks 4][nt 4][lane 32] uint4 = {bh0,bh1,bl0,bl1}
__device__ uint4 g_bf1[27*16*32];
__device__ uint4 g_bf2[27*16*32];

__device__ __forceinline__ uint32_t smem_u32(const void* p) {
    uint32_t a;
    asm("{ .reg .u64 t; cvta.to.shared.u64 t, %1; cvt.u32.u64 %0, t; }" : "=r"(a) : "l"(p));
    return a;
}

__device__ __forceinline__ void split2(float v0, float v1, uint32_t& ph, uint32_t& pl) {
    __nv_bfloat16 h0 = __float2bfloat16(v0), h1 = __float2bfloat16(v1);
    __nv_bfloat16 l0 = __float2bfloat16(v0 - __bfloat162float(h0));
    __nv_bfloat16 l1 = __float2bfloat16(v1 - __bfloat162float(h1));
    ph = ((uint32_t)__bfloat16_as_ushort(h1) << 16) | __bfloat16_as_ushort(h0);
    pl = ((uint32_t)__bfloat16_as_ushort(l1) << 16) | __bfloat16_as_ushort(l0);
}

#define MMA16816(c0,c1,c2,c3, a0,a1,a2,a3, b0,b1) \
    asm volatile("mma.sync.aligned.m16n8k16.row.col.f32.bf16.bf16.f32 " \
        "{%0,%1,%2,%3}, {%4,%5,%6,%7}, {%8,%9}, {%0,%1,%2,%3};" \
        : "+f"(c0),"+f"(c1),"+f"(c2),"+f"(c3) \
        : "r"(a0),"r"(a1),"r"(a2),"r"(a3),"r"(b0),"r"(b1))

#define LDSM4(r0,r1,r2,r3, a) \
    asm volatile("ldmatrix.sync.aligned.m8n8.x4.shared.b16 {%0,%1,%2,%3}, [%4];" \
        : "=r"(r0),"=r"(r1),"=r"(r2),"=r"(r3) : "r"(a))

// ---------------------------------------------------------------------------
// Kernel 1: build cost volume, pre-split bf16 hi/lo packed by ci-pair.
//   blockIdx.x = b*64+h, blockIdx.y = chunk (0..10).
//   chunks 0..9: 4 corr groups (2 ci-pairs, t2 owns one pair); chunk 10: concat.
// ---------------------------------------------------------------------------
__global__ __launch_bounds__(256)
void build_volume_kernel(const float* __restrict__ lg,
                         const float* __restrict__ rg,
                         const float* __restrict__ lc,
                         const float* __restrict__ rc)
{
    __shared__ float lgs[32][WW_];
    __shared__ float rgs[32][WW_];

    const int b     = blockIdx.x / HH_;
    const int h     = blockIdx.x % HH_;
    const int chunk = blockIdx.y;
    const int tid   = threadIdx.x;
    const int w     = tid & 127;
    const int t2    = tid >> 7;

    if (chunk < 10) {
        for (int i = tid; i < 32 * WW_; i += 256) {
            int ch = i >> 7, ww = i & 127;
            int cg = chunk * 32 + ch;
            lgs[ch][ww] = lg[((size_t)(b * 320 + cg) * HH_ + h) * WW_ + ww];
            rgs[ch][ww] = rg[((size_t)(b * 320 + cg) * HH_ + h) * WW_ + ww];
        }
        __syncthreads();

        // thread owns ci-pair (local groups 2*t2, 2*t2+1)
        float l0[CPG], l1[CPG];
        #pragma unroll
        for (int c = 0; c < CPG; ++c) {
            l0[c] = lgs[(2 * t2)     * CPG + c][w];
            l1[c] = lgs[(2 * t2 + 1) * CPG + c][w];
        }
        const int cp = chunk * 2 + t2;   // ci-pair index 0..19
        size_t o = (size_t)(b * 32 + cp) * DHW + (size_t)h * WW_ + w;
        #pragma unroll 4
        for (int d = 0; d < DD_; ++d) {
            float s0 = 0.f, s1 = 0.f;
            if (w >= d) {
                #pragma unroll
                for (int c = 0; c < CPG; ++c) {
                    s0 += l0[c] * rgs[(2 * t2)     * CPG + c][w - d];
                    s1 += l1[c] * rgs[(2 * t2 + 1) * CPG + c][w - d];
                }
                s0 *= (1.0f / CPG); s1 *= (1.0f / CPG);
            }
            uint32_t ph, pl;
            split2(s0, s1, ph, pl);
            g_volH[o + (size_t)d * HW] = ph;
            g_volL[o + (size_t)d * HW] = pl;
        }
    } else {
        for (int i = tid; i < 24 * WW_; i += 256) {
            int ch = i >> 7, ww = i & 127;
            lgs[ch][ww] = (ch < 12)
                ? lc[((size_t)(b * CCH + ch)      * HH_ + h) * WW_ + ww]
                : rc[((size_t)(b * CCH + (ch-12)) * HH_ + h) * WW_ + ww];
        }
        __syncthreads();
        // 12 channel-pairs x 48 d  (pairs never straddle lc/rc: 12 is even)
        for (int idx = t2; idx < 12 * DD_; idx += 2) {
            int p = idx / DD_, d = idx % DD_;
            float v0 = 0.f, v1 = 0.f;
            if (w >= d) {
                int src = (p < 6) ? w : (w - d);
                v0 = lgs[2 * p][p < 6 ? w : w - d];
                v1 = lgs[2 * p + 1][p < 6 ? w : w - d];
                (void)src;
            }
            uint32_t ph, pl;
            split2(v0, v1, ph, pl);
            size_t o = (size_t)(b * 32 + 20 + p) * DHW + (size_t)d * HW + (size_t)h * WW_ + w;
            g_volH[o] = ph;
            g_volL[o] = pl;
        }
    }
}

// ---------------------------------------------------------------------------
// Kernel 1b: prepack weights into per-lane mma B fragments (uint4: hi|lo).
// ---------------------------------------------------------------------------
__global__ void prepack_w(const float* __restrict__ w1, const float* __restrict__ w2)
{
    const int tap = blockIdx.x;   // 0..26
    for (int e = threadIdx.x; e < 512; e += 256) {
        const int ks   = e >> 7;
        const int nt   = (e >> 5) & 3;
        const int lane = e & 31;
        const int t4 = lane & 3, gg = lane >> 2;
        const int co = nt * 8 + gg;
        const int k0 = ks * 16 + t4 * 2;
        const int kk[4] = {k0, k0 + 1, k0 + 8, k0 + 9};
        const size_t idx = ((size_t)tap * 16 + ks * 4 + nt) * 32 + lane;
        {
            uint16_t uh[4], ul[4];
            #pragma unroll
            for (int i = 0; i < 4; ++i) {
                float f = w1[((size_t)co * 64 + kk[i]) * 27 + tap];
                __nv_bfloat16 hi = __float2bfloat16(f);
                uh[i] = __bfloat16_as_ushort(hi);
                ul[i] = __bfloat16_as_ushort(__float2bfloat16(f - __bfloat162float(hi)));
            }
            uint4 r;
            r.x = ((uint32_t)uh[1] << 16) | uh[0];
            r.y = ((uint32_t)uh[3] << 16) | uh[2];
            r.z = ((uint32_t)ul[1] << 16) | ul[0];
            r.w = ((uint32_t)ul[3] << 16) | ul[2];
            g_bf1[idx] = r;
        }
        {
            uint16_t uh[4], ul[4];
            #pragma unroll
            for (int i = 0; i < 4; ++i) {
                float f = (kk[i] < 32) ? w2[((size_t)co * 32 + kk[i]) * 27 + tap] : 0.f;
                __nv_bfloat16 hi = __float2bfloat16(f);
                uh[i] = __bfloat16_as_ushort(hi);
                ul[i] = __bfloat16_as_ushort(__float2bfloat16(f - __bfloat162float(hi)));
            }
            uint4 r;
            r.x = ((uint32_t)uh[1] << 16) | uh[0];
            r.y = ((uint32_t)uh[3] << 16) | uh[2];
            r.z = ((uint32_t)ul[1] << 16) | ul[0];
            r.w = ((uint32_t)ul[3] << 16) | ul[2];
            g_bf2[idx] = r;
        }
    }
}

// ---------------------------------------------------------------------------
// Kernel 2/3: conv3d 3x3x3 + BN + ReLU via mma.sync bf16 hi/lo 3-pass.
//   R15 structure (4 warps, per-warp M=32) + copy-only fills (pre-split input)
//   + register prefetch of stage s+1 before MMA(s) + STS.128 (conflict-free).
//   OUTPACK=1: write packed bf16 hi/lo x1; OUTPACK=0: write fp32.
// ---------------------------------------------------------------------------
template<int NCP, int KSTEPS, int ROWB, int OUTPACK>
__global__ __launch_bounds__(128)
void conv_mma(const uint32_t* __restrict__ inH, const uint32_t* __restrict__ inL,
              const uint4* __restrict__ bfrag,
              const float* __restrict__ gamma, const float* __restrict__ beta,
              const float* __restrict__ mean, const float* __restrict__ var,
              float* __restrict__ outF, uint32_t* __restrict__ outH,
              uint32_t* __restrict__ outL, int bz)
{
    __shared__ __align__(16) uint8_t smA[2][130 * ROWB];
    __shared__ float2 s_bn[32];
    __shared__ int s_sid[9], s_sih[9], s_stp[9], s_ns;

    const int h = blockIdx.x, d = blockIdx.y, b = blockIdx.z + bz;
    const int tid = threadIdx.x, wid = tid >> 5, lane = tid & 31;
    const int g = lane >> 2, t4 = lane & 3;

    // zero edge rows (w=-1 -> row 0, w=128 -> row 129), both bufs
    for (int i = tid; i < ROWB; i += 128) {          // ROWB bytes / 4 * 4 rows
        int nw = ROWB / 4;
        int r = i / nw, wd = i % nw;
        if (r < 4) {
            int buf = r >> 1, row = (r & 1) ? 129 : 0;
            *(uint32_t*)&smA[buf][row * ROWB + wd * 4] = 0u;
        }
    }
    if (tid < 32) {
        float iv = gamma[tid] * rsqrtf(var[tid] + 1e-5f);
        s_bn[tid] = make_float2(iv, beta[tid] - mean[tid] * iv);
    }
    if (tid == 0) {
        int ns = 0;
        for (int kd = 0; kd < 3; ++kd) {
            int id = d + kd - 1;
            if (id < 0 || id >= DD_) continue;
            for (int kh = 0; kh < 3; ++kh) {
                int ih = h + kh - 1;
                if (ih < 0 || ih >= HH_) continue;
                s_sid[ns] = id; s_sih[ns] = ih; s_stp[ns] = kd * 9 + kh * 3;
                ns++;
            }
        }
        s_ns = ns;
    }
    __syncthreads();
    const int ns = s_ns;

    const int wcol = tid;
    const uint32_t rowbase = (uint32_t)((wcol + 1) * ROWB);
    const size_t bbase = (size_t)b * NCP * DHW;

    uint4 pH[NCP / 4], pL[NCP / 4];
    {   // prologue: load stage 0
        size_t a0 = bbase + (size_t)s_sid[0] * HW + (size_t)s_sih[0] * WW_ + wcol;
        #pragma unroll
        for (int q4 = 0; q4 < NCP / 4; ++q4) {
            pH[q4].x = inH[a0 + (size_t)(q4 * 4 + 0) * DHW];
            pH[q4].y = inH[a0 + (size_t)(q4 * 4 + 1) * DHW];
            pH[q4].z = inH[a0 + (size_t)(q4 * 4 + 2) * DHW];
            pH[q4].w = inH[a0 + (size_t)(q4 * 4 + 3) * DHW];
            pL[q4].x = inL[a0 + (size_t)(q4 * 4 + 0) * DHW];
            pL[q4].y = inL[a0 + (size_t)(q4 * 4 + 1) * DHW];
            pL[q4].z = inL[a0 + (size_t)(q4 * 4 + 2) * DHW];
            pL[q4].w = inL[a0 + (size_t)(q4 * 4 + 3) * DHW];
        }
    }

    const int lj = lane >> 3, lr = lane & 7;
    const uint32_t aoff0 = (uint32_t)((wid * 32 + (lj & 1) * 8 + lr) * ROWB + (lj >> 1) * 16);
    const uint32_t baseHi = smem_u32(&smA[0][0]);
    const uint32_t baseLo = smem_u32(&smA[1][0]);

    float acc[2][4][4];
    #pragma unroll
    for (int mf = 0; mf < 2; ++mf)
        #pragma unroll
        for (int nt = 0; nt < 4; ++nt)
            #pragma unroll
            for (int i = 0; i < 4; ++i) acc[mf][nt][i] = 0.f;

    for (int s = 0; s < ns; ++s) {
        __syncthreads();   // prior stage's LDSM reads complete
        #pragma unroll
        for (int q4 = 0; q4 < NCP / 4; ++q4) {
            *(uint4*)&smA[0][rowbase + q4 * 16] = pH[q4];
            *(uint4*)&smA[1][rowbase + q4 * 16] = pL[q4];
        }
        __syncthreads();   // tile visible to all warps
        if (s + 1 < ns) {  // prefetch next stage; latency hides under MMA below
            size_t a0 = bbase + (size_t)s_sid[s+1] * HW + (size_t)s_sih[s+1] * WW_ + wcol;
            #pragma unroll
            for (int q4 = 0; q4 < NCP / 4; ++q4) {
                pH[q4].x = inH[a0 + (size_t)(q4 * 4 + 0) * DHW];
                pH[q4].y = inH[a0 + (size_t)(q4 * 4 + 1) * DHW];
                pH[q4].z = inH[a0 + (size_t)(q4 * 4 + 2) * DHW];
                pH[q4].w = inH[a0 + (size_t)(q4 * 4 + 3) * DHW];
                pL[q4].x = inL[a0 + (size_t)(q4 * 4 + 0) * DHW];
                pL[q4].y = inL[a0 + (size_t)(q4 * 4 + 1) * DHW];
                pL[q4].z = inL[a0 + (size_t)(q4 * 4 + 2) * DHW];
                pL[q4].w = inL[a0 + (size_t)(q4 * 4 + 3) * DHW];
            }
        }

        const int tapb = s_stp[s];
        #pragma unroll
        for (int kw = 0; kw < 3; ++kw) {
            const uint4* bp = bfrag + (size_t)(tapb + kw) * 512 + lane;
            #pragma unroll
            for (int ks = 0; ks < KSTEPS; ++ks) {
                uint4 Bv[4];
                #pragma unroll
                for (int nt = 0; nt < 4; ++nt)
                    Bv[nt] = bp[(ks * 4 + nt) * 32];
                const uint32_t ad = aoff0 + (uint32_t)(kw * ROWB + ks * 32);
                #pragma unroll
                for (int mf = 0; mf < 2; ++mf) {
                    const uint32_t adm = ad + (uint32_t)(mf * 16 * ROWB);
                    uint32_t ah0, ah1, ah2, ah3, al0, al1, al2, al3;
                    LDSM4(ah0, ah1, ah2, ah3, baseHi + adm);
                    LDSM4(al0, al1, al2, al3, baseLo + adm);
                    #pragma unroll
                    for (int nt = 0; nt < 4; ++nt) {
                        MMA16816(acc[mf][nt][0], acc[mf][nt][1], acc[mf][nt][2], acc[mf][nt][3],
                                 ah0, ah1, ah2, ah3, Bv[nt].x, Bv[nt].y);
                        MMA16816(acc[mf][nt][0], acc[mf][nt][1], acc[mf][nt][2], acc[mf][nt][3],
                                 ah0, ah1, ah2, ah3, Bv[nt].z, Bv[nt].w);
                        MMA16816(acc[mf][nt][0], acc[mf][nt][1], acc[mf][nt][2], acc[mf][nt][3],
                                 al0, al1, al2, al3, Bv[nt].x, Bv[nt].y);
                    }
                }
            }
        }
    }

    // ---- epilogue: BN + ReLU ----
    if (OUTPACK) {
        // packed bf16 hi/lo x1: [b][copair 16][d][h][w]
        #pragma unroll
        for (int mf = 0; mf < 2; ++mf) {
            const int wm = wid * 32 + mf * 16 + g;
            #pragma unroll
            for (int nt = 0; nt < 4; ++nt) {
                const int co = nt * 8 + t4 * 2;
                float2 bn0 = s_bn[co], bn1 = s_bn[co + 1];
                float v0 = fmaxf(acc[mf][nt][0] * bn0.x + bn0.y, 0.f);
                float v1 = fmaxf(acc[mf][nt][1] * bn1.x + bn1.y, 0.f);
                float v2 = fmaxf(acc[mf][nt][2] * bn0.x + bn0.y, 0.f);
                float v3 = fmaxf(acc[mf][nt][3] * bn1.x + bn1.y, 0.f);
                uint32_t ph0, pl0, ph1, pl1;
                split2(v0, v1, ph0, pl0);
                split2(v2, v3, ph1, pl1);
                const int copair = nt * 4 + t4;
                size_t o = (size_t)(b * 16 + copair) * DHW + (size_t)d * HW
                         + (size_t)h * WW_ + wm;
                outH[o]     = ph0;  outL[o]     = pl0;
                outH[o + 8] = ph1;  outL[o + 8] = pl1;
            }
        }
    } else {
        float* ob = outF + (size_t)(b * 32) * DHW + (size_t)d * HW + (size_t)h * WW_;
        #pragma unroll
        for (int mf = 0; mf < 2; ++mf) {
            const int wm = wid * 32 + mf * 16 + g;
            #pragma unroll
            for (int nt = 0; nt < 4; ++nt) {
                const int co = nt * 8 + t4 * 2;
                float2 bn0 = s_bn[co], bn1 = s_bn[co + 1];
                ob[(size_t)co * DHW + wm]           = fmaxf(acc[mf][nt][0] * bn0.x + bn0.y, 0.f);
                ob[(size_t)(co + 1) * DHW + wm]     = fmaxf(acc[mf][nt][1] * bn1.x + bn1.y, 0.f);
                ob[(size_t)co * DHW + wm + 8]       = fmaxf(acc[mf][nt][2] * bn0.x + bn0.y, 0.f);
                ob[(size_t)(co + 1) * DHW + wm + 8] = fmaxf(acc[mf][nt][3] * bn1.x + bn1.y, 0.f);
            }
        }
    }
}

// ---------------------------------------------------------------------------

extern "C" void kernel_launch(void* const* d_in, const int* in_sizes, int n_in,
                              void* d_out, int out_size)
{
    const float* lg = (const float*)d_in[0];
    const float* rg = (const float*)d_in[1];
    const float* lc = (const float*)d_in[2];
    const float* rc = (const float*)d_in[3];
    const float* w1 = (const float*)d_in[4];
    const float* g1 = (const float*)d_in[5];
    const float* b1 = (const float*)d_in[6];
    const float* m1 = (const float*)d_in[7];
    const float* v1 = (const float*)d_in[8];
    const float* w2 = (const float*)d_in[9];
    const float* g2 = (const float*)d_in[10];
    const float* b2 = (const float*)d_in[11];
    const float* m2 = (const float*)d_in[12];
    const float* v2 = (const float*)d_in[13];
    float* out = (float*)d_out;

    uint32_t *volH = nullptr, *volL = nullptr, *x1H = nullptr, *x1L = nullptr;
    uint4 *bf1 = nullptr, *bf2 = nullptr;
    cudaGetSymbolAddress((void**)&volH, g_volH);
    cudaGetSymbolAddress((void**)&volL, g_volL);
    cudaGetSymbolAddress((void**)&x1H,  g_x1H);
    cudaGetSymbolAddress((void**)&x1L,  g_x1L);
    cudaGetSymbolAddress((void**)&bf1,  g_bf1);
    cudaGetSymbolAddress((void**)&bf2,  g_bf2);

    // 1) cost volume (pre-split bf16 hi/lo, packed ci-pairs)
    dim3 gv(BB * HH_, 11);
    build_volume_kernel<<<gv, 256>>>(lg, rg, lc, rc);

    // 1b) weight prepack into mma fragments
    prepack_w<<<27, 256>>>(w1, w2);

    // 2) conv1 (64->32), packed output; split by batch so ncu -s 5 lands on it
    dim3 gc(HH_, DD_, 1);
    conv_mma<32, 4, 144, 1><<<gc, 128>>>(volH, volL, bf1, g1, b1, m1, v1, nullptr, x1H, x1L, 0);
    conv_mma<32, 4, 144, 1><<<gc, 128>>>(volH, volL, bf1, g1, b1, m1, v1, nullptr, x1H, x1L, 1);
    conv_mma<32, 4, 144, 1><<<gc, 128>>>(volH, volL, bf1, g1, b1, m1, v1, nullptr, x1H, x1L, 2);
    conv_mma<32, 4, 144, 1><<<gc, 128>>>(volH, volL, bf1, g1, b1, m1, v1, nullptr, x1H, x1L, 3);

    // 3) conv2 (32->32), fp32 output
    dim3 gc2(HH_, DD_, BB);
    conv_mma<16, 2, 80, 0><<<gc2, 128>>>(x1H, x1L, bf2, g2, b2, m2, v2, out, nullptr, nullptr, 0);
}